// round 10
// baseline (speedup 1.0000x reference)
#include <cuda_runtime.h>
#include <cuda_bf16.h>
#include <cstdint>

#define NB 4
#define NS 2048
#define ND 128
#define NDL 16
#define NTOP 8

#define NSEG 64
#define QSEG (NS / NSEG)   // 32

#define KSPLIT 2
#define KHALF (NS / KSPLIT)   // 1024

typedef unsigned long long ull;

// ---- scratch (device globals; no allocation allowed) ----
__device__ float g_qlow[NB * NS * NDL];
__device__ float g_klow[NB * NS * NDL];
__device__ float g_sh[NB * NS];
__device__ float g_S[(size_t)NB * NS * NS];          // 64 MB corrected scores
__device__ float g_psum[NSEG * NB * NS];             // column partial sums
__device__ float g_cinv[NB * NS];
__device__ float g_po[KSPLIT][NB * NS * ND];         // split-k partial outputs

__device__ __forceinline__ float neg_inf() { return __int_as_float(0xff800000u); }

// ---- packed f32x2 helpers ----
__device__ __forceinline__ ull pack2(float lo, float hi) {
    ull r;
    asm("mov.b64 %0, {%1, %2};" : "=l"(r) : "f"(lo), "f"(hi));
    return r;
}
__device__ __forceinline__ ull pack2dup(float v) {
    ull r;
    asm("mov.b64 %0, {%1, %1};" : "=l"(r) : "f"(v));
    return r;
}
__device__ __forceinline__ void unpack2(ull v, float& lo, float& hi) {
    asm("mov.b64 {%0, %1}, %2;" : "=f"(lo), "=f"(hi) : "l"(v));
}
__device__ __forceinline__ void fma2(ull& acc, ull a, ull b) {
    asm("fma.rn.f32x2 %0, %1, %2, %0;" : "+l"(acc) : "l"(a), "l"(b));
}

// ---- bf16 mma helpers ----
__device__ __forceinline__ void mma16816(float* c, const unsigned* a, const unsigned* b) {
    asm volatile(
        "mma.sync.aligned.m16n8k16.row.col.f32.bf16.bf16.f32 "
        "{%0,%1,%2,%3}, {%4,%5,%6,%7}, {%8,%9}, {%0,%1,%2,%3};"
        : "+f"(c[0]), "+f"(c[1]), "+f"(c[2]), "+f"(c[3])
        : "r"(a[0]), "r"(a[1]), "r"(a[2]), "r"(a[3]), "r"(b[0]), "r"(b[1]));
}
__device__ __forceinline__ unsigned short bf16bits(float x) {
    __nv_bfloat16 h = __float2bfloat16(x);
    return *(unsigned short*)&h;
}
__device__ __forceinline__ float bf16val(unsigned short u) {
    __nv_bfloat16 h = *(__nv_bfloat16*)&u;
    return __bfloat162float(h);
}

// ============================================================
// K1: low/high projections + per-(b,k) correction scalar sh
// ============================================================
__global__ void __launch_bounds__(64) k_proj(
    const float* __restrict__ Q, const float* __restrict__ K,
    const float* __restrict__ Wql, const float* __restrict__ bql,
    const float* __restrict__ Wkl, const float* __restrict__ bkl,
    const float* __restrict__ Wqh, const float* __restrict__ bqh,
    const float* __restrict__ Wkh, const float* __restrict__ bkh)
{
    int row = blockIdx.x;          // b*NS + i
    int t = threadIdx.x;
    __shared__ float qr[ND];
    __shared__ float kr[ND];
    __shared__ float qh[NDL];
    __shared__ float kh[NDL];

    qr[t]      = Q[(size_t)row * ND + t];
    qr[t + 64] = Q[(size_t)row * ND + t + 64];
    kr[t]      = K[(size_t)row * ND + t];
    kr[t + 64] = K[(size_t)row * ND + t + 64];
    __syncthreads();

    int g = t >> 4, j = t & 15;
    if (g == 0) {
        float a = bql[j];
        #pragma unroll 8
        for (int e = 0; e < ND; e++) a += qr[e] * Wql[e * NDL + j];
        g_qlow[(size_t)row * NDL + j] = a;
    } else if (g == 1) {
        float a = bkl[j];
        #pragma unroll 8
        for (int e = 0; e < ND; e++) a += kr[e] * Wkl[e * NDL + j];
        g_klow[(size_t)row * NDL + j] = a;
    } else if (g == 2) {
        float a = bqh[j];
        #pragma unroll 8
        for (int e = 0; e < ND; e++) a += qr[e] * Wqh[e * NDL + j];
        qh[j] = a;
    } else {
        float a = bkh[j];
        #pragma unroll 8
        for (int e = 0; e < ND; e++) a += kr[e] * Wkh[e * NDL + j];
        kh[j] = a;
    }
    __syncthreads();

    if (t == 0) {
        float s = 0.f;
        #pragma unroll
        for (int j2 = 0; j2 < NDL; j2++) s += qh[j2] * kh[j2];
        g_sh[row] = 0.25f * s;    // scale = 1/sqrt(16)
    }
}

// ============================================================
// K2a: masked low-rank scores -> g_S  (f32x2 packed: 2 q rows per lane)
// ============================================================
__global__ void __launch_bounds__(256) k_scores(const int* __restrict__ VL)
{
    __shared__ __align__(16) float ks[128][20];
    __shared__ __align__(16) float Ss[32][132];
    __shared__ int vls[128];

    int b  = blockIdx.z;
    int q0 = blockIdx.y * 32;
    int k0 = blockIdx.x * 128;
    int t  = threadIdx.x;

    {
        const float4* src = (const float4*)(g_klow + ((size_t)b * NS + k0) * NDL);
        #pragma unroll
        for (int u = 0; u < 2; u++) {
            int p = t + u * 256;
            float4 v = src[p];
            *(float4*)&ks[p >> 2][(p & 3) * 4] = v;
        }
    }
    if (t < 128) {
        int vlc = VL[b * NS + k0 + t];
        vlc = vlc < 0 ? 0 : (vlc > NS - 1 ? NS - 1 : vlc);
        vls[t] = vlc;
    }
    __syncthreads();

    int tq = t >> 4;             // 0..15
    int kg = t & 15;             // 0..15
    int ql0 = tq * 2;
    int qg0 = q0 + ql0, qg1 = qg0 + 1;

    ull qp2[NDL];
    {
        const float4* qp = (const float4*)(g_qlow + ((size_t)b * NS + qg0) * NDL);
        #pragma unroll
        for (int u = 0; u < 4; u++) {
            float4 v = qp[u];       // row 0
            float4 w = qp[u + 4];   // row 1
            qp2[u * 4 + 0] = pack2(v.x, w.x);
            qp2[u * 4 + 1] = pack2(v.y, w.y);
            qp2[u * 4 + 2] = pack2(v.z, w.z);
            qp2[u * 4 + 3] = pack2(v.w, w.w);
        }
    }

    #pragma unroll
    for (int i = 0; i < 8; i++) {
        int kl = kg + 16 * i;
        ull acc = 0ull;
        #pragma unroll
        for (int u = 0; u < 4; u++) {
            float4 kv = *(const float4*)&ks[kl][u * 4];
            fma2(acc, qp2[u * 4 + 0], pack2dup(kv.x));
            fma2(acc, qp2[u * 4 + 1], pack2dup(kv.y));
            fma2(acc, qp2[u * 4 + 2], pack2dup(kv.z));
            fma2(acc, qp2[u * 4 + 3], pack2dup(kv.w));
        }
        float a0, a1;
        unpack2(acc, a0, a1);
        a0 *= 0.25f; a1 *= 0.25f;
        int vlc = vls[kl];
        if (vlc == qg0) a0 += -1e9f;
        if (vlc == qg1) a1 += -1e9f;
        Ss[ql0][kl]     = a0;
        Ss[ql0 + 1][kl] = a1;
    }
    __syncthreads();

    #pragma unroll
    for (int u = 0; u < 4; u++) {
        int p = t + u * 256;
        int row = p >> 5, cg = p & 31;
        float4 v = *(const float4*)&Ss[row][cg * 4];
        *(float4*)(g_S + ((size_t)b * NS + q0 + row) * NS + k0 + cg * 4) = v;
    }
}

// ============================================================
// K2b: per-row top-8 and scatter sh into g_S
// ============================================================
__global__ void __launch_bounds__(256) k_topk()
{
    int q = blockIdx.x, b = blockIdx.y;
    int t = threadIdx.x;
    __shared__ __align__(16) float wk[NS];
    __shared__ float rv[8];
    __shared__ int ri[8];
    __shared__ int s_mi;
    __shared__ int topIdx[NTOP];

    float* Srow = g_S + ((size_t)b * NS + q) * NS;
    #pragma unroll
    for (int u = 0; u < 2; u++) {
        int p = t + u * 256;
        ((float4*)wk)[p] = ((const float4*)Srow)[p];
    }
    __syncthreads();

    float lv = neg_inf(); int li = 0;
    #pragma unroll
    for (int i = 0; i < 8; i++) {
        int k = t + i * 256;
        float v = wk[k];
        if (v > lv) { lv = v; li = k; }
    }

    for (int r = 0; r < NTOP; r++) {
        float mv = lv; int mi = li;
        #pragma unroll
        for (int o = 16; o > 0; o >>= 1) {
            float ov = __shfl_xor_sync(0xffffffffu, mv, o);
            int   oi = __shfl_xor_sync(0xffffffffu, mi, o);
            if (ov > mv || (ov == mv && oi < mi)) { mv = ov; mi = oi; }
        }
        if ((t & 31) == 0) { rv[t >> 5] = mv; ri[t >> 5] = mi; }
        __syncthreads();
        if (t == 0) {
            #pragma unroll
            for (int w = 1; w < 8; w++)
                if (rv[w] > mv || (rv[w] == mv && ri[w] < mi)) { mv = rv[w]; mi = ri[w]; }
            topIdx[r] = mi;
            s_mi = mi;
        }
        __syncthreads();
        if (r < NTOP - 1) {
            int gm = s_mi;
            if ((gm & 255) == t) {
                wk[gm] = neg_inf();
                lv = neg_inf(); li = 0;
                #pragma unroll
                for (int i = 0; i < 8; i++) {
                    int k = t + i * 256;
                    float v = wk[k];
                    if (v > lv) { lv = v; li = k; }
                }
            }
        }
    }

    if (t < NTOP) {
        int idx = topIdx[t];
        Srow[idx] = g_sh[b * NS + idx];
    }
}

// ============================================================
// K3a: partial column sum of exp over q-segments
// ============================================================
__global__ void __launch_bounds__(256) k_colpart()
{
    int k  = (blockIdx.x * 256 + threadIdx.x) * 4;
    int b  = blockIdx.y;
    int seg = blockIdx.z;
    const float* Sb = g_S + (size_t)b * NS * NS;
    int q0 = seg * QSEG;

    float4 s = make_float4(0.f, 0.f, 0.f, 0.f);
    #pragma unroll 4
    for (int q = q0; q < q0 + QSEG; q++) {
        float4 v = *(const float4*)&Sb[(size_t)q * NS + k];
        s.x += __expf(v.x);
        s.y += __expf(v.y);
        s.z += __expf(v.z);
        s.w += __expf(v.w);
    }
    *(float4*)&g_psum[((size_t)seg * NB + b) * NS + k] = s;
}

// K3b: combine segments -> 1/colsum
__global__ void __launch_bounds__(256) k_colfin()
{
    int i = blockIdx.x * 256 + threadIdx.x;   // b*NS + k
    float s = 0.f;
    #pragma unroll 8
    for (int seg = 0; seg < NSEG; seg++)
        s += g_psum[(size_t)seg * (NB * NS) + i];
    g_cinv[i] = 1.0f / s;
}

// ============================================================
// K4: tensor-core attn*V with bf16 hi/lo error compensation.
// grid (NS/64, NB, KSPLIT); block 256 = 8 warps.
// Block tile: 64q x 128d; chunk KC=32 k.
// Warp (wid&3)->q offset 16*, (wid>>2)->d offset 64*; each warp m16 x n64.
// A = exp(S)*cinv split hi/lo, stored [m][k] bf16 (stride 36).
// B = V split hi/lo, stored transposed [d][k] bf16 (stride 36).
// acc += Ah*Bh + Ah*Bl + Al*Bh  (fp32 accum; drops ~2^-16 lo*lo term)
// ============================================================
#define KC 32
#define ASTR 36
#define VSTR 36

__global__ void __launch_bounds__(256) k_out(const float* __restrict__ V)
{
    __shared__ unsigned short Ah[64][ASTR];
    __shared__ unsigned short Al[64][ASTR];
    __shared__ unsigned short Vh[128][VSTR];
    __shared__ unsigned short Vl[128][VSTR];

    int b  = blockIdx.y;
    int q0 = blockIdx.x * 64;
    int z  = blockIdx.z;
    int t  = threadIdx.x;
    int lane = t & 31;
    int wid  = t >> 5;
    int mo  = (wid & 3) * 16;    // warp q offset
    int dwo = (wid >> 2) * 64;   // warp d offset

    const float* Sb = g_S + (size_t)b * NS * NS;
    const float* ci = g_cinv + b * NS;
    const float* Vb = V + (size_t)b * NS * ND;

    float acc[8][4];
    #pragma unroll
    for (int i = 0; i < 8; i++)
        #pragma unroll
        for (int j = 0; j < 4; j++) acc[i][j] = 0.f;

    int kbeg = z * KHALF, kend = kbeg + KHALF;
    for (int kk0 = kbeg; kk0 < kend; kk0 += KC) {
        __syncthreads();
        // ---- stage A: 64q x 32k, exp*cinv, split hi/lo (512 float4, 2/thr) ----
        #pragma unroll
        for (int u = 0; u < 2; u++) {
            int p = t + u * 256;
            int row = p >> 3, kg = (p & 7) * 4;
            float4 s4 = *(const float4*)&Sb[(size_t)(q0 + row) * NS + kk0 + kg];
            float4 c4 = *(const float4*)&ci[kk0 + kg];
            float e0 = __expf(s4.x) * c4.x, e1 = __expf(s4.y) * c4.y;
            float e2 = __expf(s4.z) * c4.z, e3 = __expf(s4.w) * c4.w;
            unsigned short h0 = bf16bits(e0), h1 = bf16bits(e1);
            unsigned short h2 = bf16bits(e2), h3 = bf16bits(e3);
            uint2 hp, lp;
            hp.x = (unsigned)h0 | ((unsigned)h1 << 16);
            hp.y = (unsigned)h2 | ((unsigned)h3 << 16);
            unsigned short l0 = bf16bits(e0 - bf16val(h0));
            unsigned short l1 = bf16bits(e1 - bf16val(h1));
            unsigned short l2 = bf16bits(e2 - bf16val(h2));
            unsigned short l3 = bf16bits(e3 - bf16val(h3));
            lp.x = (unsigned)l0 | ((unsigned)l1 << 16);
            lp.y = (unsigned)l2 | ((unsigned)l3 << 16);
            *(uint2*)&Ah[row][kg] = hp;      // stride 36 halves = 72B, 8B-aligned
            *(uint2*)&Al[row][kg] = lp;
        }
        // ---- stage V transposed: 32k x 128d -> Vt[d][k] (1024 float4, 4/thr) ----
        #pragma unroll
        for (int u = 0; u < 4; u++) {
            int p = t + u * 256;
            int kk = p >> 5, d0 = (p & 31) * 4;
            float4 v4 = *(const float4*)&Vb[(size_t)(kk0 + kk) * ND + d0];
            float vv[4] = {v4.x, v4.y, v4.z, v4.w};
            #pragma unroll
            for (int j = 0; j < 4; j++) {
                unsigned short h = bf16bits(vv[j]);
                Vh[d0 + j][kk] = h;
                Vl[d0 + j][kk] = bf16bits(vv[j] - bf16val(h));
            }
        }
        __syncthreads();

        // ---- mma over 2 k16 steps ----
        #pragma unroll
        for (int ks = 0; ks < KC; ks += 16) {
            int c0 = (lane & 3) * 2 + ks;
            int r  = mo + (lane >> 2);
            unsigned ah[4], al[4];
            ah[0] = *(const unsigned*)&Ah[r][c0];
            ah[1] = *(const unsigned*)&Ah[r + 8][c0];
            ah[2] = *(const unsigned*)&Ah[r][c0 + 8];
            ah[3] = *(const unsigned*)&Ah[r + 8][c0 + 8];
            al[0] = *(const unsigned*)&Al[r][c0];
            al[1] = *(const unsigned*)&Al[r + 8][c0];
            al[2] = *(const unsigned*)&Al[r][c0 + 8];
            al[3] = *(const unsigned*)&Al[r + 8][c0 + 8];
            #pragma unroll
            for (int nt = 0; nt < 8; nt++) {
                int n = dwo + nt * 8 + (lane >> 2);
                unsigned bh[2], bl[2];
                bh[0] = *(const unsigned*)&Vh[n][c0];
                bh[1] = *(const unsigned*)&Vh[n][c0 + 8];
                bl[0] = *(const unsigned*)&Vl[n][c0];
                bl[1] = *(const unsigned*)&Vl[n][c0 + 8];
                mma16816(acc[nt], ah, bh);
                mma16816(acc[nt], ah, bl);
                mma16816(acc[nt], al, bh);
            }
        }
    }

    // ---- epilogue: write warp's m16 x n64 to split-k partial ----
    float* po = g_po[z];
    int r = q0 + mo + (lane >> 2);
    #pragma unroll
    for (int nt = 0; nt < 8; nt++) {
        int dcol = dwo + nt * 8 + (lane & 3) * 2;
        float2 v0 = make_float2(acc[nt][0], acc[nt][1]);
        float2 v1 = make_float2(acc[nt][2], acc[nt][3]);
        *(float2*)&po[(size_t)(b * NS + r) * ND + dcol] = v0;
        *(float2*)&po[(size_t)(b * NS + r + 8) * ND + dcol] = v1;
    }
}

// K5: add the two split-k halves -> final out
__global__ void __launch_bounds__(256) k_add(float* __restrict__ Out)
{
    int p = blockIdx.x * 256 + threadIdx.x;   // float4 index
    float4 a = ((const float4*)g_po[0])[p];
    float4 c = ((const float4*)g_po[1])[p];
    a.x += c.x; a.y += c.y; a.z += c.z; a.w += c.w;
    ((float4*)Out)[p] = a;
}

// ============================================================
extern "C" void kernel_launch(void* const* d_in, const int* in_sizes, int n_in,
                              void* d_out, int out_size)
{
    const float* Q   = (const float*)d_in[0];
    const float* K   = (const float*)d_in[1];
    const float* V   = (const float*)d_in[2];
    const int*   VL  = (const int*)d_in[3];
    const float* Wql = (const float*)d_in[4];
    const float* bql = (const float*)d_in[5];
    const float* Wkl = (const float*)d_in[6];
    const float* bkl = (const float*)d_in[7];
    const float* Wqh = (const float*)d_in[8];
    const float* bqh = (const float*)d_in[9];
    const float* Wkh = (const float*)d_in[10];
    const float* bkh = (const float*)d_in[11];
    float* out = (float*)d_out;

    k_proj<<<NB * NS, 64>>>(Q, K, Wql, bql, Wkl, bkl, Wqh, bqh, Wkh, bkh);

    dim3 g2(NS / 128, NS / 32, NB);
    k_scores<<<g2, 256>>>(VL);

    dim3 g2b(NS, NB);
    k_topk<<<g2b, 256>>>();

    dim3 g3(2, NB, NSEG);
    k_colpart<<<g3, 256>>>();
    k_colfin<<<(NB * NS) / 256, 256>>>();

    dim3 g4(NS / 64, NB, KSPLIT);
    k_out<<<g4, 256>>>(V);

    k_add<<<(NB * NS * ND) / 4 / 256, 256>>>(out);
}